// round 14
// baseline (speedup 1.0000x reference)
#include <cuda_runtime.h>
#include <cuda_fp16.h>
#include <cstdint>

using fp16 = __half;

constexpr int KDIM = 4096;
constexpr size_t SZ_W = (size_t)4096 * 4096;
constexpr size_t SZ_X = (size_t)8192 * 4096;

// ---------------- static device scratch (all single fp16) ----------------
__device__ fp16 g_Ut[SZ_W];       // Ut[o,a] = U[a,o]
__device__ fp16 g_Vt[SZ_W];       // Vt[i,b] = V[b,i]
__device__ fp16 g_qf[SZ_W];       // q[b,a] as fp16 (exact)
__device__ fp16 g_x[SZ_X];        // x[m,i]
__device__ fp16 g_T1[SZ_W];       // T[o,b]
__device__ fp16 g_W[SZ_W];        // Wtt[o,i]
__device__ float g_cs_part[8 * 4096];   // partial colsums of U

// ---------------- PTX helpers ----------------
__device__ __forceinline__ uint32_t smem_u32(const void* p) {
    uint32_t a;
    asm("{ .reg .u64 t; cvta.to.shared.u64 t, %1; cvt.u32.u64 %0, t; }" : "=r"(a) : "l"(p));
    return a;
}
__device__ __forceinline__ void cp16(uint32_t dst, const void* src) {
    asm volatile("cp.async.cg.shared.global [%0], [%1], 16;" :: "r"(dst), "l"(src));
}
__device__ __forceinline__ void ldsm4(uint32_t* r, uint32_t addr) {
    asm volatile("ldmatrix.sync.aligned.m8n8.x4.shared.b16 {%0,%1,%2,%3}, [%4];"
                 : "=r"(r[0]), "=r"(r[1]), "=r"(r[2]), "=r"(r[3]) : "r"(addr));
}
__device__ __forceinline__ void mma16816(float* c, const uint32_t* a, const uint32_t* b) {
    asm volatile("mma.sync.aligned.m16n8k16.row.col.f32.f16.f16.f32 "
                 "{%0,%1,%2,%3}, {%4,%5,%6,%7}, {%8,%9}, {%0,%1,%2,%3};"
                 : "+f"(c[0]), "+f"(c[1]), "+f"(c[2]), "+f"(c[3])
                 : "r"(a[0]), "r"(a[1]), "r"(a[2]), "r"(a[3]), "r"(b[0]), "r"(b[1]));
}
__device__ __forceinline__ uint32_t sw128(uint32_t o) { return o ^ ((o >> 3) & 0x70); }

// ---------------- preprocessing ----------------
template <int WHICH>   // 0: U -> g_Ut (transposed). 1: V -> g_Vt (transposed).
__global__ void transconv(const float* __restrict__ src) {
    __shared__ float t[32][33];
    int c0 = blockIdx.x * 32, r0 = blockIdx.y * 32;
    int tx = threadIdx.x, ty = threadIdx.y;
#pragma unroll
    for (int j = 0; j < 4; j++)
        t[ty + j * 8][tx] = src[(size_t)(r0 + ty + j * 8) * 4096 + c0 + tx];
    __syncthreads();
#pragma unroll
    for (int j = 0; j < 4; j++) {
        int c = c0 + ty + j * 8;
        float v = t[tx][ty + j * 8];
        fp16* dst = (WHICH == 0) ? g_Ut : g_Vt;
        dst[(size_t)c * 4096 + r0 + tx] = __float2half_rn(v);
    }
}

__global__ void convx(const float* __restrict__ xin) {
    size_t i = (size_t)blockIdx.x * 256 + threadIdx.x;
    float4 v = ((const float4*)xin)[i];
    union { fp16 b[4]; uint2 u; } H;
    H.b[0] = __float2half_rn(v.x);
    H.b[1] = __float2half_rn(v.y);
    H.b[2] = __float2half_rn(v.z);
    H.b[3] = __float2half_rn(v.w);
    ((uint2*)g_x)[i] = H.u;
}

__global__ void convq(const int* __restrict__ q) {
    size_t i = (size_t)blockIdx.x * 256 + threadIdx.x;
    int4 v = ((const int4*)q)[i];
    union { fp16 b[4]; uint2 u; } H;
    H.b[0] = __float2half_rn((float)v.x);
    H.b[1] = __float2half_rn((float)v.y);
    H.b[2] = __float2half_rn((float)v.z);
    H.b[3] = __float2half_rn((float)v.w);
    ((uint2*)g_qf)[i] = H.u;
}

__global__ void colsum_part(const float* __restrict__ U) {
    int col = blockIdx.x * 256 + threadIdx.x;
    int seg = blockIdx.y;
    float s = 0.f;
    for (int k = seg * 512; k < seg * 512 + 512; k++)
        s += U[(size_t)k * 4096 + col];
    g_cs_part[seg * 4096 + col] = s;
}

// ---------------- HMMA GEMM (fp16 m16n8k16, fp32 accum, single x single) ----------------
// C[M,N] = sum_k A[m,k]*B[n,k] (both K-major). ONE pass per GEMM.
// MODE 0: A=Ut, B=q.   epi: v*dq_mul - dq_sub*colsum[row] -> T1 (fp16)
// MODE 1: A=T1, B=Vt.  epi: v / scaleWH[col]              -> W  (fp16)
// MODE 2: A=x,  B=W.   epi: v + bias[col]                 -> out (fp32)
// NEW: 128 threads (4 warps, 2x2 grid, warp tile 64x64), CTA 128x128, 2 CTAs/SM.
// Combines round-13's cross-CTA overlap with round-11's 128B/MMA smem efficiency.
constexpr int BM = 128, BN = 128, BK = 64, NCHUNK = KDIM / BK;
constexpr int NTHREADS = 128;
constexpr uint32_t TILE_A = 128 * 128;   // 16 KB
constexpr uint32_t TILE_B = 128 * 128;   // 16 KB
constexpr uint32_t OFF_A = 0, OFF_B = TILE_A;
constexpr uint32_t ST = TILE_A + TILE_B;           // 32 KB per stage
constexpr uint32_t SMEM_SZ = 2 * ST + 1024;        // 65 KB -> two CTAs fit
constexpr int WM = 64, WN = 64, MT = WM / 16, NT = WN / 8;

template <int MODE>
__global__ __launch_bounds__(NTHREADS, 2) void hgemm(const float* __restrict__ aux,
                                                     float* __restrict__ outp) {
    const fp16 *A, *B;
    if (MODE == 0) { A = g_Ut; B = g_qf; }
    if (MODE == 1) { A = g_T1; B = g_Vt; }
    if (MODE == 2) { A = g_x;  B = g_W; }

    extern __shared__ char dsm[];
    const uint32_t sbase = (smem_u32(dsm) + 1023u) & ~1023u;

    const int tid = threadIdx.x;
    const int wid = tid >> 5, lane = tid & 31;
    const int warp_m = wid >> 1;   // 0..1  (64 rows)
    const int warp_n = wid & 1;    // 0..1  (64 cols)
    const int m0 = blockIdx.y * BM, n0 = blockIdx.x * BN;

    float acc[MT][NT][4];
#pragma unroll
    for (int a = 0; a < MT; a++)
#pragma unroll
        for (int b = 0; b < NT; b++)
#pragma unroll
            for (int d = 0; d < 4; d++) acc[a][b][d] = 0.f;

    auto load_stage = [&](int s, int c) {
        const uint32_t sb = sbase + (uint32_t)s * ST;
        const int k0 = c * BK;
#pragma unroll
        for (int t = 0; t < 8; t++) {          // A: 1024 slots
            int idx = tid + t * NTHREADS;
            int r = idx >> 3, cc = idx & 7;
            uint32_t sw = sw128((uint32_t)(r * 128 + cc * 16));
            cp16(sb + OFF_A + sw, A + (size_t)(m0 + r) * KDIM + k0 + cc * 8);
        }
#pragma unroll
        for (int t = 0; t < 8; t++) {          // B: 1024 slots
            int idx = tid + t * NTHREADS;
            int r = idx >> 3, cc = idx & 7;
            uint32_t sw = sw128((uint32_t)(r * 128 + cc * 16));
            cp16(sb + OFF_B + sw, B + (size_t)(n0 + r) * KDIM + k0 + cc * 8);
        }
        asm volatile("cp.async.commit_group;");
    };

    load_stage(0, 0);

    const uint32_t a_row = (uint32_t)(warp_m * WM + (lane & 15));
    const uint32_t a_kb  = (uint32_t)((lane >> 4) << 4);
    const uint32_t b_row = (uint32_t)(warp_n * WN + ((lane >> 4) << 3) + (lane & 7));
    const uint32_t b_kb  = (uint32_t)(((lane >> 3) & 1) << 4);

    for (int c = 0; c < NCHUNK; c++) {
        asm volatile("cp.async.wait_group 0;");
        __syncthreads();
        if (c + 1 < NCHUNK) load_stage((c + 1) & 1, c + 1);

        const uint32_t sb = sbase + (uint32_t)(c & 1) * ST;
#pragma unroll
        for (int ks = 0; ks < BK / 16; ks++) {
            uint32_t ar[MT][4], br[NT][2];
#pragma unroll
            for (int mt = 0; mt < MT; mt++) {
                uint32_t o = sw128((a_row + mt * 16) * 128 + ks * 32 + a_kb);
                ldsm4(ar[mt], sb + OFF_A + o);
            }
#pragma unroll
            for (int np = 0; np < NT / 2; np++) {
                uint32_t o = sw128((b_row + np * 16) * 128 + ks * 32 + b_kb);
                uint32_t tmp[4];
                ldsm4(tmp, sb + OFF_B + o);
                br[2 * np][0] = tmp[0]; br[2 * np][1] = tmp[1];
                br[2 * np + 1][0] = tmp[2]; br[2 * np + 1][1] = tmp[3];
            }
#pragma unroll
            for (int mt = 0; mt < MT; mt++)
#pragma unroll
                for (int nt = 0; nt < NT; nt++)
                    mma16816(acc[mt][nt], ar[mt], br[nt]);
        }
    }

    // ---------------- epilogue ----------------
    const int gid = lane >> 2, tig = lane & 3;
    float dq_mul = 0.f, dq_sub = 0.f;
    if (MODE == 0) { float sc = aux[0]; dq_mul = sc * (2.0f / 15.0f); dq_sub = sc; }

    float c0f[NT], c1f[NT];
#pragma unroll
    for (int nt = 0; nt < NT; nt++) {
        int col = n0 + warp_n * WN + nt * 8 + tig * 2;
        if (MODE == 1) { c0f[nt] = 1.0f / aux[col]; c1f[nt] = 1.0f / aux[col + 1]; }
        else if (MODE == 2) { c0f[nt] = aux[col]; c1f[nt] = aux[col + 1]; }
        else { c0f[nt] = 0.f; c1f[nt] = 0.f; }
    }

#pragma unroll
    for (int mt = 0; mt < MT; mt++) {
        int r0 = m0 + warp_m * WM + mt * 16 + gid;
        int r1 = r0 + 8;
        float sub0 = 0.f, sub1 = 0.f;
        if (MODE == 0) {
            float cs0 = 0.f, cs1 = 0.f;
#pragma unroll
            for (int p = 0; p < 8; p++) {
                cs0 += g_cs_part[p * 4096 + r0];
                cs1 += g_cs_part[p * 4096 + r1];
            }
            sub0 = dq_sub * cs0; sub1 = dq_sub * cs1;
        }
#pragma unroll
        for (int nt = 0; nt < NT; nt++) {
            int col = n0 + warp_n * WN + nt * 8 + tig * 2;
            float v0 = acc[mt][nt][0], v1 = acc[mt][nt][1];
            float v2 = acc[mt][nt][2], v3 = acc[mt][nt][3];
            if (MODE == 0) {
                v0 = v0 * dq_mul - sub0; v1 = v1 * dq_mul - sub0;
                v2 = v2 * dq_mul - sub1; v3 = v3 * dq_mul - sub1;
            } else if (MODE == 1) {
                v0 *= c0f[nt]; v1 *= c1f[nt]; v2 *= c0f[nt]; v3 *= c1f[nt];
            } else {
                v0 += c0f[nt]; v1 += c1f[nt]; v2 += c0f[nt]; v3 += c1f[nt];
            }
            if (MODE == 2) {
                *(float2*)(outp + (size_t)r0 * 4096 + col) = make_float2(v0, v1);
                *(float2*)(outp + (size_t)r1 * 4096 + col) = make_float2(v2, v3);
            } else {
                fp16* C = (MODE == 0) ? g_T1 : g_W;
                union { fp16 b[2]; uint32_t u; } h;
                h.b[0] = __float2half_rn(v0); h.b[1] = __float2half_rn(v1);
                *(uint32_t*)(C + (size_t)r0 * 4096 + col) = h.u;
                h.b[0] = __float2half_rn(v2); h.b[1] = __float2half_rn(v3);
                *(uint32_t*)(C + (size_t)r1 * 4096 + col) = h.u;
            }
        }
    }
}

// ---------------- host ----------------
extern "C" void kernel_launch(void* const* d_in, const int* in_sizes, int n_in,
                              void* d_out, int out_size) {
    const float* x       = (const float*)d_in[0];
    const int*   qweight = (const int*)  d_in[1];
    const float* scale   = (const float*)d_in[2];
    const float* scaleWH = (const float*)d_in[3];
    const float* bias    = (const float*)d_in[4];
    const float* U       = (const float*)d_in[5];
    const float* V       = (const float*)d_in[6];
    float*       out     = (float*)d_out;

    cudaFuncSetAttribute(hgemm<0>, cudaFuncAttributeMaxDynamicSharedMemorySize, SMEM_SZ);
    cudaFuncSetAttribute(hgemm<1>, cudaFuncAttributeMaxDynamicSharedMemorySize, SMEM_SZ);
    cudaFuncSetAttribute(hgemm<2>, cudaFuncAttributeMaxDynamicSharedMemorySize, SMEM_SZ);

    dim3 tb32(32, 8);
    colsum_part<<<dim3(16, 8), 256>>>(U);                            // 0
    transconv<0><<<dim3(128, 128), tb32>>>(U);                       // 1
    convq<<<16384, 256>>>(qweight);                                  // 2
    hgemm<0><<<dim3(32, 32), NTHREADS, SMEM_SZ>>>(scale, nullptr);   // 3 <- profiled
    transconv<1><<<dim3(128, 128), tb32>>>(V);                       // 4
    hgemm<1><<<dim3(32, 32), NTHREADS, SMEM_SZ>>>(scaleWH, nullptr); // 5
    convx<<<(unsigned)(SZ_X / 4 / 256), 256>>>(x);                   // 6
    hgemm<2><<<dim3(32, 64), NTHREADS, SMEM_SZ>>>(bias, out);        // 7
}

// round 15
// speedup vs baseline: 1.1185x; 1.1185x over previous
#include <cuda_runtime.h>
#include <cuda_fp16.h>
#include <cstdint>

using fp16 = __half;

constexpr int KDIM = 4096;
constexpr size_t SZ_W = (size_t)4096 * 4096;
constexpr size_t SZ_X = (size_t)8192 * 4096;

// ---------------- static device scratch (all single fp16) ----------------
__device__ fp16 g_Ut[SZ_W];       // Ut[o,a] = U[a,o]
__device__ fp16 g_Vt[SZ_W];       // Vt[i,b] = V[b,i]
__device__ fp16 g_qf[SZ_W];       // q[b,a] as fp16 (exact)
__device__ fp16 g_x[SZ_X];        // x[m,i]
__device__ fp16 g_T1[SZ_W];       // T[o,b]
__device__ fp16 g_W[SZ_W];        // Wtt[o,i]
__device__ float g_cs_part[8 * 4096];   // partial colsums of U

// ---------------- PTX helpers ----------------
__device__ __forceinline__ uint32_t smem_u32(const void* p) {
    uint32_t a;
    asm("{ .reg .u64 t; cvta.to.shared.u64 t, %1; cvt.u32.u64 %0, t; }" : "=r"(a) : "l"(p));
    return a;
}
__device__ __forceinline__ void cp16(uint32_t dst, const void* src) {
    asm volatile("cp.async.cg.shared.global [%0], [%1], 16;" :: "r"(dst), "l"(src));
}
__device__ __forceinline__ void ldsm4(uint32_t* r, uint32_t addr) {
    asm volatile("ldmatrix.sync.aligned.m8n8.x4.shared.b16 {%0,%1,%2,%3}, [%4];"
                 : "=r"(r[0]), "=r"(r[1]), "=r"(r[2]), "=r"(r[3]) : "r"(addr));
}
__device__ __forceinline__ void mma16816(float* c, const uint32_t* a, const uint32_t* b) {
    asm volatile("mma.sync.aligned.m16n8k16.row.col.f32.f16.f16.f32 "
                 "{%0,%1,%2,%3}, {%4,%5,%6,%7}, {%8,%9}, {%0,%1,%2,%3};"
                 : "+f"(c[0]), "+f"(c[1]), "+f"(c[2]), "+f"(c[3])
                 : "r"(a[0]), "r"(a[1]), "r"(a[2]), "r"(a[3]), "r"(b[0]), "r"(b[1]));
}
__device__ __forceinline__ uint32_t sw128(uint32_t o) { return o ^ ((o >> 3) & 0x70); }

// ---------------- consolidated preprocessing (one launch) ----------------
// block ranges:
//   [0, 16384)        transconv U  -> g_Ut   (128x128 blocks of 32x32)
//   [16384, 32768)    transconv V  -> g_Vt
//   [32768, 49152)    convq        -> g_qf
//   [49152, 81920)    convx        -> g_x
//   [81920, 82048)    colsum_part  -> g_cs_part
__global__ __launch_bounds__(256) void prep_all(const float* __restrict__ U,
                                                const float* __restrict__ V,
                                                const int*   __restrict__ q,
                                                const float* __restrict__ x) {
    __shared__ float t[32][33];
    const int bi = blockIdx.x;
    const int tid = threadIdx.x;

    if (bi < 32768) {
        // transpose-convert U or V
        const float* src = (bi < 16384) ? U : V;
        fp16* dst = (bi < 16384) ? g_Ut : g_Vt;
        int b = bi & 16383;
        int c0 = (b & 127) * 32, r0 = (b >> 7) * 32;
        int tx = tid & 31, ty = tid >> 5;   // 32 x 8
#pragma unroll
        for (int j = 0; j < 4; j++)
            t[ty + j * 8][tx] = src[(size_t)(r0 + ty + j * 8) * 4096 + c0 + tx];
        __syncthreads();
#pragma unroll
        for (int j = 0; j < 4; j++) {
            int c = c0 + ty + j * 8;
            dst[(size_t)c * 4096 + r0 + tx] = __float2half_rn(t[tx][ty + j * 8]);
        }
    } else if (bi < 49152) {
        // convq: int32 -> fp16 (exact)
        size_t i = (size_t)(bi - 32768) * 256 + tid;
        int4 v = ((const int4*)q)[i];
        union { fp16 b[4]; uint2 u; } H;
        H.b[0] = __float2half_rn((float)v.x);
        H.b[1] = __float2half_rn((float)v.y);
        H.b[2] = __float2half_rn((float)v.z);
        H.b[3] = __float2half_rn((float)v.w);
        ((uint2*)g_qf)[i] = H.u;
    } else if (bi < 81920) {
        // convx: fp32 -> fp16
        size_t i = (size_t)(bi - 49152) * 256 + tid;
        float4 v = ((const float4*)x)[i];
        union { fp16 b[4]; uint2 u; } H;
        H.b[0] = __float2half_rn(v.x);
        H.b[1] = __float2half_rn(v.y);
        H.b[2] = __float2half_rn(v.z);
        H.b[3] = __float2half_rn(v.w);
        ((uint2*)g_x)[i] = H.u;
    } else {
        // colsum partials over U: 128 blocks, seg = idx>>4, colblock = idx&15
        int r = bi - 81920;
        int seg = r >> 4;
        int col = (r & 15) * 256 + tid;
        float s = 0.f;
        for (int k = seg * 512; k < seg * 512 + 512; k++)
            s += U[(size_t)k * 4096 + col];
        g_cs_part[seg * 4096 + col] = s;
    }
}

// ---------------- HMMA GEMM (fp16 m16n8k16, fp32 accum, single x single) ----------------
// C[M,N] = sum_k A[m,k]*B[n,k] (both K-major). ONE pass per GEMM.
// MODE 0: A=Ut, B=q.   epi: v*dq_mul - dq_sub*colsum[row] -> T1 (fp16)
// MODE 1: A=T1, B=Vt.  epi: v / scaleWH[col]              -> W  (fp16)
// MODE 2: A=x,  B=W.   epi: v + bias[col]                 -> out (fp32)
// Round-13 shape (CTA 128x128, warp 64x32, 2 CTAs/SM) + 3-stage BK=64 pipeline.
constexpr int BM = 128, BN = 128, BK = 64, NCHUNK = KDIM / BK;
constexpr uint32_t TILE_A = 128 * 128;   // 16 KB
constexpr uint32_t TILE_B = 128 * 128;   // 16 KB
constexpr uint32_t OFF_A = 0, OFF_B = TILE_A;
constexpr uint32_t ST = TILE_A + TILE_B;           // 32 KB per stage
constexpr int STAGES = 3;
constexpr uint32_t SMEM_SZ = STAGES * ST + 1024;   // 97 KB -> 2 CTAs = 194 KB/SM
constexpr int WM = 64, WN = 32, MT = WM / 16, NT = WN / 8;

template <int MODE>
__global__ __launch_bounds__(256, 2) void hgemm(const float* __restrict__ aux,
                                                float* __restrict__ outp) {
    const fp16 *A, *B;
    if (MODE == 0) { A = g_Ut; B = g_qf; }
    if (MODE == 1) { A = g_T1; B = g_Vt; }
    if (MODE == 2) { A = g_x;  B = g_W; }

    extern __shared__ char dsm[];
    const uint32_t sbase = (smem_u32(dsm) + 1023u) & ~1023u;

    const int tid = threadIdx.x;
    const int wid = tid >> 5, lane = tid & 31;
    const int warp_m = wid >> 2;   // 0..1  (64 rows)
    const int warp_n = wid & 3;    // 0..3  (32 cols)
    const int m0 = blockIdx.y * BM, n0 = blockIdx.x * BN;

    float acc[MT][NT][4];
#pragma unroll
    for (int a = 0; a < MT; a++)
#pragma unroll
        for (int b = 0; b < NT; b++)
#pragma unroll
            for (int d = 0; d < 4; d++) acc[a][b][d] = 0.f;

    auto load_stage = [&](int s, int c) {
        const uint32_t sb = sbase + (uint32_t)s * ST;
        const int k0 = c * BK;
#pragma unroll
        for (int t = 0; t < 4; t++) {          // A: 1024 slots
            int idx = tid + t * 256;
            int r = idx >> 3, cc = idx & 7;
            uint32_t sw = sw128((uint32_t)(r * 128 + cc * 16));
            cp16(sb + OFF_A + sw, A + (size_t)(m0 + r) * KDIM + k0 + cc * 8);
        }
#pragma unroll
        for (int t = 0; t < 4; t++) {          // B: 1024 slots
            int idx = tid + t * 256;
            int r = idx >> 3, cc = idx & 7;
            uint32_t sw = sw128((uint32_t)(r * 128 + cc * 16));
            cp16(sb + OFF_B + sw, B + (size_t)(n0 + r) * KDIM + k0 + cc * 8);
        }
        asm volatile("cp.async.commit_group;");
    };

    load_stage(0, 0);
    load_stage(1, 1);

    const uint32_t a_row = (uint32_t)(warp_m * WM + (lane & 15));
    const uint32_t a_kb  = (uint32_t)((lane >> 4) << 4);
    const uint32_t b_row = (uint32_t)(warp_n * WN + ((lane >> 4) << 3) + (lane & 7));
    const uint32_t b_kb  = (uint32_t)(((lane >> 3) & 1) << 4);

    int sidx = 0;   // stage index of chunk c (mod 3)
    for (int c = 0; c < NCHUNK; c++) {
        // stage c's load was committed 2 iterations ago; allow 1 newer pending
        asm volatile("cp.async.wait_group 1;");
        __syncthreads();
        // slot (c+2)%3 == slot of chunk c-1; barrier above proves all warps done with it
        int pidx = sidx + 2; if (pidx >= 3) pidx -= 3;
        if (c + 2 < NCHUNK) load_stage(pidx, c + 2);
        else asm volatile("cp.async.commit_group;");   // dummy keeps group arithmetic exact

        const uint32_t sb = sbase + (uint32_t)sidx * ST;
#pragma unroll
        for (int ks = 0; ks < BK / 16; ks++) {
            uint32_t ar[MT][4], br[NT][2];
#pragma unroll
            for (int mt = 0; mt < MT; mt++) {
                uint32_t o = sw128((a_row + mt * 16) * 128 + ks * 32 + a_kb);
                ldsm4(ar[mt], sb + OFF_A + o);
            }
#pragma unroll
            for (int np = 0; np < NT / 2; np++) {
                uint32_t o = sw128((b_row + np * 16) * 128 + ks * 32 + b_kb);
                uint32_t tmp[4];
                ldsm4(tmp, sb + OFF_B + o);
                br[2 * np][0] = tmp[0]; br[2 * np][1] = tmp[1];
                br[2 * np + 1][0] = tmp[2]; br[2 * np + 1][1] = tmp[3];
            }
#pragma unroll
            for (int mt = 0; mt < MT; mt++)
#pragma unroll
                for (int nt = 0; nt < NT; nt++)
                    mma16816(acc[mt][nt], ar[mt], br[nt]);
        }
        if (++sidx == 3) sidx = 0;
    }

    // ---------------- epilogue ----------------
    const int gid = lane >> 2, tig = lane & 3;
    float dq_mul = 0.f, dq_sub = 0.f;
    if (MODE == 0) { float sc = aux[0]; dq_mul = sc * (2.0f / 15.0f); dq_sub = sc; }

    float c0f[NT], c1f[NT];
#pragma unroll
    for (int nt = 0; nt < NT; nt++) {
        int col = n0 + warp_n * WN + nt * 8 + tig * 2;
        if (MODE == 1) { c0f[nt] = 1.0f / aux[col]; c1f[nt] = 1.0f / aux[col + 1]; }
        else if (MODE == 2) { c0f[nt] = aux[col]; c1f[nt] = aux[col + 1]; }
        else { c0f[nt] = 0.f; c1f[nt] = 0.f; }
    }

#pragma unroll
    for (int mt = 0; mt < MT; mt++) {
        int r0 = m0 + warp_m * WM + mt * 16 + gid;
        int r1 = r0 + 8;
        float sub0 = 0.f, sub1 = 0.f;
        if (MODE == 0) {
            float cs0 = 0.f, cs1 = 0.f;
#pragma unroll
            for (int p = 0; p < 8; p++) {
                cs0 += g_cs_part[p * 4096 + r0];
                cs1 += g_cs_part[p * 4096 + r1];
            }
            sub0 = dq_sub * cs0; sub1 = dq_sub * cs1;
        }
#pragma unroll
        for (int nt = 0; nt < NT; nt++) {
            int col = n0 + warp_n * WN + nt * 8 + tig * 2;
            float v0 = acc[mt][nt][0], v1 = acc[mt][nt][1];
            float v2 = acc[mt][nt][2], v3 = acc[mt][nt][3];
            if (MODE == 0) {
                v0 = v0 * dq_mul - sub0; v1 = v1 * dq_mul - sub0;
                v2 = v2 * dq_mul - sub1; v3 = v3 * dq_mul - sub1;
            } else if (MODE == 1) {
                v0 *= c0f[nt]; v1 *= c1f[nt]; v2 *= c0f[nt]; v3 *= c1f[nt];
            } else {
                v0 += c0f[nt]; v1 += c1f[nt]; v2 += c0f[nt]; v3 += c1f[nt];
            }
            if (MODE == 2) {
                *(float2*)(outp + (size_t)r0 * 4096 + col) = make_float2(v0, v1);
                *(float2*)(outp + (size_t)r1 * 4096 + col) = make_float2(v2, v3);
            } else {
                fp16* C = (MODE == 0) ? g_T1 : g_W;
                union { fp16 b[2]; uint32_t u; } h;
                h.b[0] = __float2half_rn(v0); h.b[1] = __float2half_rn(v1);
                *(uint32_t*)(C + (size_t)r0 * 4096 + col) = h.u;
                h.b[0] = __float2half_rn(v2); h.b[1] = __float2half_rn(v3);
                *(uint32_t*)(C + (size_t)r1 * 4096 + col) = h.u;
            }
        }
    }
}

// ---------------- host ----------------
extern "C" void kernel_launch(void* const* d_in, const int* in_sizes, int n_in,
                              void* d_out, int out_size) {
    const float* x       = (const float*)d_in[0];
    const int*   qweight = (const int*)  d_in[1];
    const float* scale   = (const float*)d_in[2];
    const float* scaleWH = (const float*)d_in[3];
    const float* bias    = (const float*)d_in[4];
    const float* U       = (const float*)d_in[5];
    const float* V       = (const float*)d_in[6];
    float*       out     = (float*)d_out;

    cudaFuncSetAttribute(hgemm<0>, cudaFuncAttributeMaxDynamicSharedMemorySize, SMEM_SZ);
    cudaFuncSetAttribute(hgemm<1>, cudaFuncAttributeMaxDynamicSharedMemorySize, SMEM_SZ);
    cudaFuncSetAttribute(hgemm<2>, cudaFuncAttributeMaxDynamicSharedMemorySize, SMEM_SZ);

    prep_all<<<82048, 256>>>(U, V, qweight, x);                    // 0
    hgemm<0><<<dim3(32, 32), 256, SMEM_SZ>>>(scale, nullptr);      // 1
    hgemm<1><<<dim3(32, 32), 256, SMEM_SZ>>>(scaleWH, nullptr);    // 2
    hgemm<2><<<dim3(32, 64), 256, SMEM_SZ>>>(bias, out);           // 3 <- profiled
}

// round 16
// speedup vs baseline: 1.1209x; 1.0021x over previous
#include <cuda_runtime.h>
#include <cuda_fp16.h>
#include <cstdint>

using fp16 = __half;

constexpr int KDIM = 4096;
constexpr size_t SZ_W = (size_t)4096 * 4096;
constexpr size_t SZ_X = (size_t)8192 * 4096;

// ---------------- static device scratch (all single fp16) ----------------
__device__ fp16 g_Ut[SZ_W];       // Ut[o,a] = U[a,o]
__device__ fp16 g_Vt[SZ_W];       // Vt[i,b] = V[b,i]
__device__ fp16 g_qf[SZ_W];       // q[b,a] as fp16 (exact)
__device__ fp16 g_x[SZ_X];        // x[m,i] / scaleWH[i]  (rescale folded here)
__device__ fp16 g_T1[SZ_W];       // T[o,b]
__device__ fp16 g_W[SZ_W];        // Wtt[o,i]  (UNscaled now)
__device__ float g_cs_part[8 * 4096];   // partial colsums of U

// ---------------- PTX helpers ----------------
__device__ __forceinline__ uint32_t smem_u32(const void* p) {
    uint32_t a;
    asm("{ .reg .u64 t; cvta.to.shared.u64 t, %1; cvt.u32.u64 %0, t; }" : "=r"(a) : "l"(p));
    return a;
}
__device__ __forceinline__ void cp16(uint32_t dst, const void* src) {
    asm volatile("cp.async.cg.shared.global [%0], [%1], 16;" :: "r"(dst), "l"(src));
}
__device__ __forceinline__ void ldsm4(uint32_t* r, uint32_t addr) {
    asm volatile("ldmatrix.sync.aligned.m8n8.x4.shared.b16 {%0,%1,%2,%3}, [%4];"
                 : "=r"(r[0]), "=r"(r[1]), "=r"(r[2]), "=r"(r[3]) : "r"(addr));
}
__device__ __forceinline__ void mma16816(float* c, const uint32_t* a, const uint32_t* b) {
    asm volatile("mma.sync.aligned.m16n8k16.row.col.f32.f16.f16.f32 "
                 "{%0,%1,%2,%3}, {%4,%5,%6,%7}, {%8,%9}, {%0,%1,%2,%3};"
                 : "+f"(c[0]), "+f"(c[1]), "+f"(c[2]), "+f"(c[3])
                 : "r"(a[0]), "r"(a[1]), "r"(a[2]), "r"(a[3]), "r"(b[0]), "r"(b[1]));
}
__device__ __forceinline__ uint32_t sw128(uint32_t o) { return o ^ ((o >> 3) & 0x70); }

// ---------------- consolidated preprocessing (one launch) ----------------
// block ranges:
//   [0, 16384)        transconv U  -> g_Ut
//   [16384, 32768)    transconv V  -> g_Vt
//   [32768, 49152)    convq        -> g_qf
//   [49152, 81920)    convx (with 1/scaleWH fold) -> g_x
//   [81920, 82048)    colsum_part  -> g_cs_part
__global__ __launch_bounds__(256) void prep_all(const float* __restrict__ U,
                                                const float* __restrict__ V,
                                                const int*   __restrict__ q,
                                                const float* __restrict__ x,
                                                const float* __restrict__ sWH) {
    __shared__ float t[32][33];
    const int bi = blockIdx.x;
    const int tid = threadIdx.x;

    if (bi < 32768) {
        const float* src = (bi < 16384) ? U : V;
        fp16* dst = (bi < 16384) ? g_Ut : g_Vt;
        int b = bi & 16383;
        int c0 = (b & 127) * 32, r0 = (b >> 7) * 32;
        int tx = tid & 31, ty = tid >> 5;   // 32 x 8
#pragma unroll
        for (int j = 0; j < 4; j++)
            t[ty + j * 8][tx] = src[(size_t)(r0 + ty + j * 8) * 4096 + c0 + tx];
        __syncthreads();
#pragma unroll
        for (int j = 0; j < 4; j++) {
            int c = c0 + ty + j * 8;
            dst[(size_t)c * 4096 + r0 + tx] = __float2half_rn(t[tx][ty + j * 8]);
        }
    } else if (bi < 49152) {
        size_t i = (size_t)(bi - 32768) * 256 + tid;
        int4 v = ((const int4*)q)[i];
        union { fp16 b[4]; uint2 u; } H;
        H.b[0] = __float2half_rn((float)v.x);
        H.b[1] = __float2half_rn((float)v.y);
        H.b[2] = __float2half_rn((float)v.z);
        H.b[3] = __float2half_rn((float)v.w);
        ((uint2*)g_qf)[i] = H.u;
    } else if (bi < 81920) {
        // convx with scaleWH fold: x'[m,i] = x[m,i] / sWH[i]
        size_t i = (size_t)(bi - 49152) * 256 + tid;   // float4 index
        size_t col4 = i & (4096 / 4 - 1);              // i-dim float4 index
        float4 v = ((const float4*)x)[i];
        float4 s = ((const float4*)sWH)[col4];
        union { fp16 b[4]; uint2 u; } H;
        H.b[0] = __float2half_rn(v.x / s.x);
        H.b[1] = __float2half_rn(v.y / s.y);
        H.b[2] = __float2half_rn(v.z / s.z);
        H.b[3] = __float2half_rn(v.w / s.w);
        ((uint2*)g_x)[i] = H.u;
    } else {
        int r = bi - 81920;
        int seg = r >> 4;
        int col = (r & 15) * 256 + tid;
        float s = 0.f;
        for (int k = seg * 512; k < seg * 512 + 512; k++)
            s += U[(size_t)k * 4096 + col];
        g_cs_part[seg * 4096 + col] = s;
    }
}

// ---------------- HMMA GEMM (fp16 m16n8k16, fp32 accum, single x single) ----------------
// C[M,N] = sum_k A[m,k]*B[n,k] (both K-major). ONE pass per GEMM.
// MODE 0: A=Ut, B=q.   epi: v*dq_mul - dq_sub*colsum[row] -> T1 (fp16)
// MODE 1: A=T1, B=Vt.  epi: none (scaleWH folded into x)  -> W  (fp16)
// MODE 2: A=x', B=W.   epi: v + bias[col]                 -> out (fp32)
// Round-13/15 shape: CTA 128x128, warp 64x32, 2 CTAs/SM, 3-stage BK=64 pipeline.
constexpr int BM = 128, BN = 128, BK = 64, NCHUNK = KDIM / BK;
constexpr uint32_t TILE_A = 128 * 128;   // 16 KB
constexpr uint32_t TILE_B = 128 * 128;   // 16 KB
constexpr uint32_t OFF_A = 0, OFF_B = TILE_A;
constexpr uint32_t ST = TILE_A + TILE_B;           // 32 KB per stage
constexpr int STAGES = 3;
constexpr uint32_t SMEM_SZ = STAGES * ST + 1024;   // 97 KB -> 2 CTAs = 194 KB/SM
constexpr int WM = 64, WN = 32, MT = WM / 16, NT = WN / 8;

template <int MODE>
__global__ __launch_bounds__(256, 2) void hgemm(const float* __restrict__ aux,
                                                float* __restrict__ outp) {
    const fp16 *A, *B;
    if (MODE == 0) { A = g_Ut; B = g_qf; }
    if (MODE == 1) { A = g_T1; B = g_Vt; }
    if (MODE == 2) { A = g_x;  B = g_W; }

    extern __shared__ char dsm[];
    const uint32_t sbase = (smem_u32(dsm) + 1023u) & ~1023u;

    const int tid = threadIdx.x;
    const int wid = tid >> 5, lane = tid & 31;
    const int warp_m = wid >> 2;   // 0..1  (64 rows)
    const int warp_n = wid & 3;    // 0..3  (32 cols)
    const int m0 = blockIdx.y * BM, n0 = blockIdx.x * BN;

    float acc[MT][NT][4];
#pragma unroll
    for (int a = 0; a < MT; a++)
#pragma unroll
        for (int b = 0; b < NT; b++)
#pragma unroll
            for (int d = 0; d < 4; d++) acc[a][b][d] = 0.f;

    auto load_stage = [&](int s, int c) {
        const uint32_t sb = sbase + (uint32_t)s * ST;
        const int k0 = c * BK;
#pragma unroll
        for (int t = 0; t < 4; t++) {          // A: 1024 slots
            int idx = tid + t * 256;
            int r = idx >> 3, cc = idx & 7;
            uint32_t sw = sw128((uint32_t)(r * 128 + cc * 16));
            cp16(sb + OFF_A + sw, A + (size_t)(m0 + r) * KDIM + k0 + cc * 8);
        }
#pragma unroll
        for (int t = 0; t < 4; t++) {          // B: 1024 slots
            int idx = tid + t * 256;
            int r = idx >> 3, cc = idx & 7;
            uint32_t sw = sw128((uint32_t)(r * 128 + cc * 16));
            cp16(sb + OFF_B + sw, B + (size_t)(n0 + r) * KDIM + k0 + cc * 8);
        }
        asm volatile("cp.async.commit_group;");
    };

    load_stage(0, 0);
    load_stage(1, 1);

    const uint32_t a_row = (uint32_t)(warp_m * WM + (lane & 15));
    const uint32_t a_kb  = (uint32_t)((lane >> 4) << 4);
    const uint32_t b_row = (uint32_t)(warp_n * WN + ((lane >> 4) << 3) + (lane & 7));
    const uint32_t b_kb  = (uint32_t)(((lane >> 3) & 1) << 4);

    int sidx = 0;
    for (int c = 0; c < NCHUNK; c++) {
        // proven order (round 7/8): per-thread wait, THEN barrier, THEN prefetch
        asm volatile("cp.async.wait_group 1;");
        __syncthreads();
        int pidx = sidx + 2; if (pidx >= 3) pidx -= 3;
        if (c + 2 < NCHUNK) load_stage(pidx, c + 2);
        else asm volatile("cp.async.commit_group;");

        const uint32_t sb = sbase + (uint32_t)sidx * ST;
#pragma unroll
        for (int ks = 0; ks < BK / 16; ks++) {
            uint32_t ar[MT][4], br[NT][2];
#pragma unroll
            for (int mt = 0; mt < MT; mt++) {
                uint32_t o = sw128((a_row + mt * 16) * 128 + ks * 32 + a_kb);
                ldsm4(ar[mt], sb + OFF_A + o);
            }
#pragma unroll
            for (int np = 0; np < NT / 2; np++) {
                uint32_t o = sw128((b_row + np * 16) * 128 + ks * 32 + b_kb);
                uint32_t tmp[4];
                ldsm4(tmp, sb + OFF_B + o);
                br[2 * np][0] = tmp[0]; br[2 * np][1] = tmp[1];
                br[2 * np + 1][0] = tmp[2]; br[2 * np + 1][1] = tmp[3];
            }
#pragma unroll
            for (int mt = 0; mt < MT; mt++)
#pragma unroll
                for (int nt = 0; nt < NT; nt++)
                    mma16816(acc[mt][nt], ar[mt], br[nt]);
        }
        if (++sidx == 3) sidx = 0;
    }

    // ---------------- epilogue ----------------
    const int gid = lane >> 2, tig = lane & 3;
    float dq_mul = 0.f, dq_sub = 0.f;
    if (MODE == 0) { float sc = aux[0]; dq_mul = sc * (2.0f / 15.0f); dq_sub = sc; }

    float c0f[NT], c1f[NT];
#pragma unroll
    for (int nt = 0; nt < NT; nt++) {
        int col = n0 + warp_n * WN + nt * 8 + tig * 2;
        if (MODE == 2) { c0f[nt] = aux[col]; c1f[nt] = aux[col + 1]; }
        else { c0f[nt] = 0.f; c1f[nt] = 0.f; }
    }

#pragma unroll
    for (int mt = 0; mt < MT; mt++) {
        int r0 = m0 + warp_m * WM + mt * 16 + gid;
        int r1 = r0 + 8;
        float sub0 = 0.f, sub1 = 0.f;
        if (MODE == 0) {
            float cs0 = 0.f, cs1 = 0.f;
#pragma unroll
            for (int p = 0; p < 8; p++) {
                cs0 += g_cs_part[p * 4096 + r0];
                cs1 += g_cs_part[p * 4096 + r1];
            }
            sub0 = dq_sub * cs0; sub1 = dq_sub * cs1;
        }
#pragma unroll
        for (int nt = 0; nt < NT; nt++) {
            int col = n0 + warp_n * WN + nt * 8 + tig * 2;
            float v0 = acc[mt][nt][0], v1 = acc[mt][nt][1];
            float v2 = acc[mt][nt][2], v3 = acc[mt][nt][3];
            if (MODE == 0) {
                v0 = v0 * dq_mul - sub0; v1 = v1 * dq_mul - sub0;
                v2 = v2 * dq_mul - sub1; v3 = v3 * dq_mul - sub1;
            } else if (MODE == 2) {
                v0 += c0f[nt]; v1 += c1f[nt]; v2 += c0f[nt]; v3 += c1f[nt];
            }
            if (MODE == 2) {
                *(float2*)(outp + (size_t)r0 * 4096 + col) = make_float2(v0, v1);
                *(float2*)(outp + (size_t)r1 * 4096 + col) = make_float2(v2, v3);
            } else {
                fp16* C = (MODE == 0) ? g_T1 : g_W;
                union { fp16 b[2]; uint32_t u; } h;
                h.b[0] = __float2half_rn(v0); h.b[1] = __float2half_rn(v1);
                *(uint32_t*)(C + (size_t)r0 * 4096 + col) = h.u;
                h.b[0] = __float2half_rn(v2); h.b[1] = __float2half_rn(v3);
                *(uint32_t*)(C + (size_t)r1 * 4096 + col) = h.u;
            }
        }
    }
}

// ---------------- host ----------------
extern "C" void kernel_launch(void* const* d_in, const int* in_sizes, int n_in,
                              void* d_out, int out_size) {
    const float* x       = (const float*)d_in[0];
    const int*   qweight = (const int*)  d_in[1];
    const float* scale   = (const float*)d_in[2];
    const float* scaleWH = (const float*)d_in[3];
    const float* bias    = (const float*)d_in[4];
    const float* U       = (const float*)d_in[5];
    const float* V       = (const float*)d_in[6];
    float*       out     = (float*)d_out;

    cudaFuncSetAttribute(hgemm<0>, cudaFuncAttributeMaxDynamicSharedMemorySize, SMEM_SZ);
    cudaFuncSetAttribute(hgemm<1>, cudaFuncAttributeMaxDynamicSharedMemorySize, SMEM_SZ);
    cudaFuncSetAttribute(hgemm<2>, cudaFuncAttributeMaxDynamicSharedMemorySize, SMEM_SZ);

    prep_all<<<82048, 256>>>(U, V, qweight, x, scaleWH);           // 0
    hgemm<0><<<dim3(32, 32), 256, SMEM_SZ>>>(scale, nullptr);      // 1
    hgemm<1><<<dim3(32, 32), 256, SMEM_SZ>>>(nullptr, nullptr);    // 2
    hgemm<2><<<dim3(32, 64), 256, SMEM_SZ>>>(bias, out);           // 3 <- profiled
}